// round 7
// baseline (speedup 1.0000x reference)
#include <cuda_runtime.h>
#include <cuda_fp16.h>

// Problem constants: N=100000 nodes, E=1600000 edges, HID=64
#define MAXN 100000
#define MAXE 1600000
#define HID 64
#define NB_SCAN ((MAXN + 255) / 256)   // 391 scan blocks

// ---------------- scratch (no allocations allowed) ----------------
__device__ int g_is64;
__device__ __align__(16) int    g_cnt[MAXN];
__device__ __align__(16) int    g_rowstart[MAXN];
__device__ __align__(16) int    g_cursor[MAXN];
__device__ __align__(16) int    g_bsum[NB_SCAN + 1];
__device__ __align__(16) int2   g_csr[MAXE];        // {src, norm bits}
__device__ __align__(16) float  g_dinv[MAXN];
__device__ __align__(16) __half g_bufA[MAXN * HID]; // features (gather source)
__device__ __align__(16) __half g_bufB[MAXN * HID]; // aggregated (GEMM input)

// ---------------- edge-index dtype detection (one warp) ----------------
__global__ void detect_kernel(const int* __restrict__ ei32) {
    int lane = threadIdx.x;
    int v = ei32[2 * (lane * 2) + 1] | ei32[2 * (lane * 2 + 1) + 1];
    int allzero = __all_sync(0xffffffffu, v == 0);
    if (lane == 0) g_is64 = allzero;
}

__global__ void zero_cnt_kernel(int n) {
    int i = blockIdx.x * blockDim.x + threadIdx.x;
    if (i < n) g_cnt[i] = 0;
}

__global__ void count_kernel(const int* __restrict__ ei32, int e) {
    int i = blockIdx.x * blockDim.x + threadIdx.x;
    if (i >= e) return;
    int d;
    if (g_is64) d = (int)((const long long*)ei32)[e + i];
    else        d = ei32[e + i];
    atomicAdd(&g_cnt[d], 1);
}

// ---------------- prefix scan (dinv fused into pass 1) ----------------
__global__ void scan1_kernel(int n) {
    __shared__ int wsum[8];
    int i = blockIdx.x * 256 + threadIdx.x;
    int lane = threadIdx.x & 31, w = threadIdx.x >> 5;
    int v = (i < n) ? g_cnt[i] : 0;
    if (i < n) g_dinv[i] = rsqrtf((float)v + 1.0f);
    int s = v;
#pragma unroll
    for (int o = 1; o < 32; o <<= 1) {
        int t = __shfl_up_sync(0xffffffffu, s, o);
        if (lane >= o) s += t;
    }
    if (lane == 31) wsum[w] = s;
    __syncthreads();
    if (w == 0) {
        int ws = (lane < 8) ? wsum[lane] : 0;
#pragma unroll
        for (int o = 1; o < 8; o <<= 1) {
            int t = __shfl_up_sync(0xffffffffu, ws, o);
            if (lane >= o) ws += t;
        }
        if (lane < 8) wsum[lane] = ws;
    }
    __syncthreads();
    int incl = s + ((w > 0) ? wsum[w - 1] : 0);
    if (i < n) g_rowstart[i] = incl - v;
    if (threadIdx.x == 255) g_bsum[blockIdx.x] = incl;
}

__global__ void scan2_kernel(int nb) {
    __shared__ int wsum[16];
    int tid = threadIdx.x;
    int lane = tid & 31, w = tid >> 5;
    int v = (tid < nb) ? g_bsum[tid] : 0;
    int s = v;
#pragma unroll
    for (int o = 1; o < 32; o <<= 1) {
        int t = __shfl_up_sync(0xffffffffu, s, o);
        if (lane >= o) s += t;
    }
    if (lane == 31) wsum[w] = s;
    __syncthreads();
    if (w == 0) {
        int ws = (lane < 16) ? wsum[lane] : 0;
#pragma unroll
        for (int o = 1; o < 16; o <<= 1) {
            int t = __shfl_up_sync(0xffffffffu, ws, o);
            if (lane >= o) ws += t;
        }
        if (lane < 16) wsum[lane] = ws;
    }
    __syncthreads();
    int incl = s + ((w > 0) ? wsum[w - 1] : 0);
    if (tid < nb) g_bsum[tid] = incl - v;
}

__global__ void scan3_kernel(int n) {
    int i = blockIdx.x * 256 + threadIdx.x;
    if (i < n) {
        int rs = g_rowstart[i] + g_bsum[blockIdx.x];
        g_rowstart[i] = rs;
        g_cursor[i] = rs;
    }
}

// ---------------- CSR fill ----------------
__global__ void fill_kernel(const int* __restrict__ ei32, int e) {
    int i = blockIdx.x * blockDim.x + threadIdx.x;
    if (i >= e) return;
    int s, d;
    if (g_is64) {
        const long long* e64 = (const long long*)ei32;
        s = (int)e64[i];
        d = (int)e64[e + i];
    } else {
        s = ei32[i];
        d = ei32[e + i];
    }
    int pos = atomicAdd(&g_cursor[d], 1);
    float nrm = g_dinv[s] * g_dinv[d];
    g_csr[pos] = make_int2(s, __float_as_int(nrm));
}

// ---------------- layer 1 GEMM: x(N,3) @ W1(3,64) -> bufA (fp16) ----------
__global__ void gemm_in3_kernel(const float* __restrict__ x,
                                const float* __restrict__ W1, int n) {
    int idx = blockIdx.x * blockDim.x + threadIdx.x;
    int node = idx >> 6;
    int f = idx & 63;
    if (node >= n) return;
    float x0 = x[node * 3 + 0];
    float x1 = x[node * 3 + 1];
    float x2 = x[node * 3 + 2];
    float acc = fmaf(x0, W1[f], fmaf(x1, W1[64 + f], x2 * W1[128 + f]));
    g_bufA[node * 64 + f] = __float2half_rn(acc);
}

// ---------------- CSR gather (warp per node, edge-split halves) ----------
// lane = half*16 + c ; lane group `half` handles its half of the edge list,
// lane c owns features [4c,4c+4). fp32 accumulate, fp16 store.
__global__ __launch_bounds__(256) void gather_kernel(int n) {
    int gtid = blockIdx.x * blockDim.x + threadIdx.x;
    int node = gtid >> 5;
    if (node >= n) return;
    int lane = threadIdx.x & 31;
    int c = lane & 15;
    int half = lane >> 4;

    int beg = g_rowstart[node];
    int cnt = g_cnt[node];
    int h = (cnt + 1) >> 1;
    int myBeg = beg + (half ? h : 0);
    int myCnt = half ? (cnt - h) : h;

    const uint2* __restrict__ A = (const uint2*)g_bufA;  // row = 16 uint2
    float4 acc = make_float4(0.f, 0.f, 0.f, 0.f);
    if (half == 0) {   // self loop contribution
        float di = g_dinv[node];
        float s2 = di * di;
        uint2 sv = __ldg(&A[node * 16 + c]);
        float2 a0 = __half22float2(*(const __half2*)&sv.x);
        float2 a1 = __half22float2(*(const __half2*)&sv.y);
        acc = make_float4(a0.x * s2, a0.y * s2, a1.x * s2, a1.y * s2);
    }

    int j = 0;
    for (; j + 3 < myCnt; j += 4) {
        int2 e0 = __ldg(&g_csr[myBeg + j]);
        int2 e1 = __ldg(&g_csr[myBeg + j + 1]);
        int2 e2 = __ldg(&g_csr[myBeg + j + 2]);
        int2 e3 = __ldg(&g_csr[myBeg + j + 3]);
        uint2 v0 = __ldg(&A[e0.x * 16 + c]);
        uint2 v1 = __ldg(&A[e1.x * 16 + c]);
        uint2 v2 = __ldg(&A[e2.x * 16 + c]);
        uint2 v3 = __ldg(&A[e3.x * 16 + c]);
        float n0 = __int_as_float(e0.y), n1 = __int_as_float(e1.y);
        float n2 = __int_as_float(e2.y), n3 = __int_as_float(e3.y);
        float2 p, q;
        p = __half22float2(*(const __half2*)&v0.x); q = __half22float2(*(const __half2*)&v0.y);
        acc.x = fmaf(p.x, n0, acc.x); acc.y = fmaf(p.y, n0, acc.y);
        acc.z = fmaf(q.x, n0, acc.z); acc.w = fmaf(q.y, n0, acc.w);
        p = __half22float2(*(const __half2*)&v1.x); q = __half22float2(*(const __half2*)&v1.y);
        acc.x = fmaf(p.x, n1, acc.x); acc.y = fmaf(p.y, n1, acc.y);
        acc.z = fmaf(q.x, n1, acc.z); acc.w = fmaf(q.y, n1, acc.w);
        p = __half22float2(*(const __half2*)&v2.x); q = __half22float2(*(const __half2*)&v2.y);
        acc.x = fmaf(p.x, n2, acc.x); acc.y = fmaf(p.y, n2, acc.y);
        acc.z = fmaf(q.x, n2, acc.z); acc.w = fmaf(q.y, n2, acc.w);
        p = __half22float2(*(const __half2*)&v3.x); q = __half22float2(*(const __half2*)&v3.y);
        acc.x = fmaf(p.x, n3, acc.x); acc.y = fmaf(p.y, n3, acc.y);
        acc.z = fmaf(q.x, n3, acc.z); acc.w = fmaf(q.y, n3, acc.w);
    }
    for (; j < myCnt; j++) {
        int2 e0 = __ldg(&g_csr[myBeg + j]);
        uint2 v0 = __ldg(&A[e0.x * 16 + c]);
        float n0 = __int_as_float(e0.y);
        float2 p = __half22float2(*(const __half2*)&v0.x);
        float2 q = __half22float2(*(const __half2*)&v0.y);
        acc.x = fmaf(p.x, n0, acc.x); acc.y = fmaf(p.y, n0, acc.y);
        acc.z = fmaf(q.x, n0, acc.z); acc.w = fmaf(q.y, n0, acc.w);
    }

    // combine the two halves (lane c += lane c+16)
    acc.x += __shfl_down_sync(0xffffffffu, acc.x, 16);
    acc.y += __shfl_down_sync(0xffffffffu, acc.y, 16);
    acc.z += __shfl_down_sync(0xffffffffu, acc.z, 16);
    acc.w += __shfl_down_sync(0xffffffffu, acc.w, 16);

    if (half == 0) {
        __half2 h0 = __floats2half2_rn(acc.x, acc.y);
        __half2 h1 = __floats2half2_rn(acc.z, acc.w);
        uint2 outv;
        outv.x = *(const unsigned*)&h0;
        outv.y = *(const unsigned*)&h1;
        ((uint2*)g_bufB)[node * 16 + c] = outv;
    }
}

// ---------------- 64x64 GEMM, fused input bias+ReLU: bufB(f16) -> bufA(f16)
__global__ __launch_bounds__(256) void gemm64_kernel(const float* __restrict__ bias_in,
                                                     const float* __restrict__ W, int n) {
    __shared__ __align__(16) float xs[4 * 64];
    int f = threadIdx.x & 63;
    int ty = threadIdx.x >> 6;

    float wcol[64];
#pragma unroll
    for (int k = 0; k < 64; k++) wcol[k] = W[k * 64 + f];

    for (int base = blockIdx.x * 4; base < n; base += gridDim.x * 4) {
        int node = base + ty;
        float v = 0.0f;
        if (node < n)
            v = fmaxf(__half2float(g_bufB[node * 64 + f]) + bias_in[f], 0.0f);
        xs[ty * 64 + f] = v;
        __syncthreads();

        float acc = 0.0f;
        const float4* xr = (const float4*)&xs[ty * 64];
#pragma unroll
        for (int k4 = 0; k4 < 16; k4++) {
            float4 xv = xr[k4];
            acc = fmaf(xv.x, wcol[4 * k4 + 0], acc);
            acc = fmaf(xv.y, wcol[4 * k4 + 1], acc);
            acc = fmaf(xv.z, wcol[4 * k4 + 2], acc);
            acc = fmaf(xv.w, wcol[4 * k4 + 3], acc);
        }
        if (node < n) g_bufA[node * 64 + f] = __float2half_rn(acc);
        __syncthreads();
    }
}

// ---------------- fused last GEMM + MLP head ----------------
// acc = (relu(bufB+b3) @ Wm1)[f] ; h = relu(acc+bm1[f]) ; out = sigmoid(sum h*Wm2[f] + bm2)
__global__ __launch_bounds__(256) void gemm64_mlp_kernel(const float* __restrict__ b3,
                                                         const float* __restrict__ Wm1,
                                                         const float* __restrict__ bm1,
                                                         const float* __restrict__ Wm2,
                                                         const float* __restrict__ bm2,
                                                         float* __restrict__ out, int n) {
    __shared__ __align__(16) float xs[4 * 64];
    __shared__ float psum[8];      // 2 warps per node-row, 4 rows
    int f = threadIdx.x & 63;
    int ty = threadIdx.x >> 6;
    int lane = threadIdx.x & 31;
    int wh = (threadIdx.x >> 5) & 1;  // which warp within the 64-thread row

    float wcol[64];
#pragma unroll
    for (int k = 0; k < 64; k++) wcol[k] = Wm1[k * 64 + f];
    float bm1f = bm1[f];
    float wm2f = Wm2[f];
    float bm2v = bm2[0];

    for (int base = blockIdx.x * 4; base < n; base += gridDim.x * 4) {
        int node = base + ty;
        float v = 0.0f;
        if (node < n)
            v = fmaxf(__half2float(g_bufB[node * 64 + f]) + b3[f], 0.0f);
        xs[ty * 64 + f] = v;
        __syncthreads();

        float acc = 0.0f;
        const float4* xr = (const float4*)&xs[ty * 64];
#pragma unroll
        for (int k4 = 0; k4 < 16; k4++) {
            float4 xv = xr[k4];
            acc = fmaf(xv.x, wcol[4 * k4 + 0], acc);
            acc = fmaf(xv.y, wcol[4 * k4 + 1], acc);
            acc = fmaf(xv.z, wcol[4 * k4 + 2], acc);
            acc = fmaf(xv.w, wcol[4 * k4 + 3], acc);
        }
        float hpart = fmaxf(acc + bm1f, 0.0f) * wm2f;
#pragma unroll
        for (int o = 16; o > 0; o >>= 1)
            hpart += __shfl_xor_sync(0xffffffffu, hpart, o);
        if (lane == 0) psum[ty * 2 + wh] = hpart;
        __syncthreads();
        if (f == 0 && node < n) {
            float z = psum[ty * 2] + psum[ty * 2 + 1] + bm2v;
            out[node] = 1.0f / (1.0f + __expf(-z));
        }
        __syncthreads();
    }
}

// ---------------- launch ----------------
extern "C" void kernel_launch(void* const* d_in, const int* in_sizes, int n_in,
                              void* d_out, int out_size) {
    const float* x    = (const float*)d_in[0];
    const int*   ei32 = (const int*)d_in[1];
    const float* W1  = (const float*)d_in[2];
    const float* b1  = (const float*)d_in[3];
    const float* W2  = (const float*)d_in[4];
    const float* b2  = (const float*)d_in[5];
    const float* W3  = (const float*)d_in[6];
    const float* b3  = (const float*)d_in[7];
    const float* Wm1 = (const float*)d_in[8];
    const float* bm1 = (const float*)d_in[9];
    const float* Wm2 = (const float*)d_in[10];
    const float* bm2 = (const float*)d_in[11];
    float* out = (float*)d_out;

    int n = in_sizes[0] / 3;   // 100000
    int e = in_sizes[1] / 2;   // 1600000

    const int T = 256;
    int gN   = (n + T - 1) / T;
    int gE   = (e + T - 1) / T;
    int gNF  = (n * 64 + T - 1) / T;
    int gGA  = (n * 32 + T - 1) / T;
    int gGemm = 592;
    int nb = gN;

    // ---- CSR build ----
    detect_kernel<<<1, 32>>>(ei32);
    zero_cnt_kernel<<<gN, T>>>(n);
    count_kernel<<<gE, T>>>(ei32, e);
    scan1_kernel<<<nb, 256>>>(n);
    scan2_kernel<<<1, 512>>>(nb);
    scan3_kernel<<<nb, 256>>>(n);
    fill_kernel<<<gE, T>>>(ei32, e);

    // ---- layer 1 ----
    gemm_in3_kernel<<<gNF, T>>>(x, W1, n);
    gather_kernel<<<gGA, T>>>(n);
    // ---- layer 2 ----
    gemm64_kernel<<<gGemm, T>>>(b1, W2, n);
    gather_kernel<<<gGA, T>>>(n);
    // ---- layer 3 ----
    gemm64_kernel<<<gGemm, T>>>(b2, W3, n);
    gather_kernel<<<gGA, T>>>(n);
    // ---- fused last GEMM + MLP head ----
    gemm64_mlp_kernel<<<gGemm, T>>>(b3, Wm1, bm1, Wm2, bm2, out, n);
}

// round 8
// speedup vs baseline: 1.0147x; 1.0147x over previous
#include <cuda_runtime.h>
#include <cuda_fp16.h>

// Problem constants: N=100000 nodes, E=1600000 edges, HID=64
#define MAXN 100000
#define MAXE 1600000
#define HID 64
#define NB_SCAN ((MAXN + 255) / 256)   // 391 scan blocks

// ---------------- scratch (no allocations allowed) ----------------
__device__ int g_is64;
__device__ __align__(16) int    g_cnt[MAXN];
__device__ __align__(16) int    g_rowstart[MAXN];
__device__ __align__(16) int    g_cursor[MAXN];
__device__ __align__(16) int    g_bsum[NB_SCAN + 1];
__device__ __align__(16) int2   g_csr[MAXE];        // {src, norm bits}
__device__ __align__(16) float  g_dinv[MAXN];
__device__ __align__(16) __half g_bufA[MAXN * HID]; // features (gather source)
__device__ __align__(16) __half g_bufB[MAXN * HID]; // aggregated (GEMM input)

// ---------------- edge-index dtype detection (one warp) ----------------
__global__ void detect_kernel(const int* __restrict__ ei32) {
    int lane = threadIdx.x;
    int v = ei32[2 * (lane * 2) + 1] | ei32[2 * (lane * 2 + 1) + 1];
    int allzero = __all_sync(0xffffffffu, v == 0);
    if (lane == 0) g_is64 = allzero;
}

__global__ void zero_cnt_kernel(int n) {
    int i = blockIdx.x * blockDim.x + threadIdx.x;
    if (i < n) g_cnt[i] = 0;
}

__global__ void count_kernel(const int* __restrict__ ei32, int e) {
    int i = blockIdx.x * blockDim.x + threadIdx.x;
    if (i >= e) return;
    int d;
    if (g_is64) d = (int)((const long long*)ei32)[e + i];
    else        d = ei32[e + i];
    atomicAdd(&g_cnt[d], 1);
}

// ---------------- prefix scan (dinv fused into pass 1) ----------------
__global__ void scan1_kernel(int n) {
    __shared__ int wsum[8];
    int i = blockIdx.x * 256 + threadIdx.x;
    int lane = threadIdx.x & 31, w = threadIdx.x >> 5;
    int v = (i < n) ? g_cnt[i] : 0;
    if (i < n) g_dinv[i] = rsqrtf((float)v + 1.0f);
    int s = v;
#pragma unroll
    for (int o = 1; o < 32; o <<= 1) {
        int t = __shfl_up_sync(0xffffffffu, s, o);
        if (lane >= o) s += t;
    }
    if (lane == 31) wsum[w] = s;
    __syncthreads();
    if (w == 0) {
        int ws = (lane < 8) ? wsum[lane] : 0;
#pragma unroll
        for (int o = 1; o < 8; o <<= 1) {
            int t = __shfl_up_sync(0xffffffffu, ws, o);
            if (lane >= o) ws += t;
        }
        if (lane < 8) wsum[lane] = ws;
    }
    __syncthreads();
    int incl = s + ((w > 0) ? wsum[w - 1] : 0);
    if (i < n) g_rowstart[i] = incl - v;
    if (threadIdx.x == 255) g_bsum[blockIdx.x] = incl;
}

__global__ void scan2_kernel(int nb) {
    __shared__ int wsum[16];
    int tid = threadIdx.x;
    int lane = tid & 31, w = tid >> 5;
    int v = (tid < nb) ? g_bsum[tid] : 0;
    int s = v;
#pragma unroll
    for (int o = 1; o < 32; o <<= 1) {
        int t = __shfl_up_sync(0xffffffffu, s, o);
        if (lane >= o) s += t;
    }
    if (lane == 31) wsum[w] = s;
    __syncthreads();
    if (w == 0) {
        int ws = (lane < 16) ? wsum[lane] : 0;
#pragma unroll
        for (int o = 1; o < 16; o <<= 1) {
            int t = __shfl_up_sync(0xffffffffu, ws, o);
            if (lane >= o) ws += t;
        }
        if (lane < 16) wsum[lane] = ws;
    }
    __syncthreads();
    int incl = s + ((w > 0) ? wsum[w - 1] : 0);
    if (tid < nb) g_bsum[tid] = incl - v;
}

__global__ void scan3_kernel(int n) {
    int i = blockIdx.x * 256 + threadIdx.x;
    if (i < n) {
        int rs = g_rowstart[i] + g_bsum[blockIdx.x];
        g_rowstart[i] = rs;
        g_cursor[i] = rs;
    }
}

// ---------------- CSR fill ----------------
__global__ void fill_kernel(const int* __restrict__ ei32, int e) {
    int i = blockIdx.x * blockDim.x + threadIdx.x;
    if (i >= e) return;
    int s, d;
    if (g_is64) {
        const long long* e64 = (const long long*)ei32;
        s = (int)e64[i];
        d = (int)e64[e + i];
    } else {
        s = ei32[i];
        d = ei32[e + i];
    }
    int pos = atomicAdd(&g_cursor[d], 1);
    float nrm = g_dinv[s] * g_dinv[d];
    g_csr[pos] = make_int2(s, __float_as_int(nrm));
}

// ---------------- layer 1 GEMM: x(N,3) @ W1(3,64) -> bufA (fp16) ----------
__global__ void gemm_in3_kernel(const float* __restrict__ x,
                                const float* __restrict__ W1, int n) {
    int idx = blockIdx.x * blockDim.x + threadIdx.x;
    int node = idx >> 6;
    int f = idx & 63;
    if (node >= n) return;
    float x0 = x[node * 3 + 0];
    float x1 = x[node * 3 + 1];
    float x2 = x[node * 3 + 2];
    float acc = fmaf(x0, W1[f], fmaf(x1, W1[64 + f], x2 * W1[128 + f]));
    g_bufA[node * 64 + f] = __float2half_rn(acc);
}

// ---------------- CSR gather: 16 lanes/node, unroll x4 ----------------
// lane c owns features [4c,4c+4) (8 B). fp32 accumulate, fp16 store.
__global__ __launch_bounds__(256) void gather_kernel(int n) {
    int idx = blockIdx.x * blockDim.x + threadIdx.x;
    int node = idx >> 4;
    int c = idx & 15;
    if (node >= n) return;
    int beg = g_rowstart[node];
    int cnt = g_cnt[node];
    const uint2* __restrict__ A = (const uint2*)g_bufA;  // row = 16 uint2

    float di = g_dinv[node];
    float s2 = di * di;
    uint2 sv = __ldg(&A[node * 16 + c]);
    float2 a0 = __half22float2(*(const __half2*)&sv.x);
    float2 a1 = __half22float2(*(const __half2*)&sv.y);
    float4 acc = make_float4(a0.x * s2, a0.y * s2, a1.x * s2, a1.y * s2);

    int j = 0;
    for (; j + 3 < cnt; j += 4) {
        int2 e0 = __ldg(&g_csr[beg + j]);
        int2 e1 = __ldg(&g_csr[beg + j + 1]);
        int2 e2 = __ldg(&g_csr[beg + j + 2]);
        int2 e3 = __ldg(&g_csr[beg + j + 3]);
        uint2 v0 = __ldg(&A[e0.x * 16 + c]);
        uint2 v1 = __ldg(&A[e1.x * 16 + c]);
        uint2 v2 = __ldg(&A[e2.x * 16 + c]);
        uint2 v3 = __ldg(&A[e3.x * 16 + c]);
        float n0 = __int_as_float(e0.y), n1 = __int_as_float(e1.y);
        float n2 = __int_as_float(e2.y), n3 = __int_as_float(e3.y);
        float2 p, q;
        p = __half22float2(*(const __half2*)&v0.x); q = __half22float2(*(const __half2*)&v0.y);
        acc.x = fmaf(p.x, n0, acc.x); acc.y = fmaf(p.y, n0, acc.y);
        acc.z = fmaf(q.x, n0, acc.z); acc.w = fmaf(q.y, n0, acc.w);
        p = __half22float2(*(const __half2*)&v1.x); q = __half22float2(*(const __half2*)&v1.y);
        acc.x = fmaf(p.x, n1, acc.x); acc.y = fmaf(p.y, n1, acc.y);
        acc.z = fmaf(q.x, n1, acc.z); acc.w = fmaf(q.y, n1, acc.w);
        p = __half22float2(*(const __half2*)&v2.x); q = __half22float2(*(const __half2*)&v2.y);
        acc.x = fmaf(p.x, n2, acc.x); acc.y = fmaf(p.y, n2, acc.y);
        acc.z = fmaf(q.x, n2, acc.z); acc.w = fmaf(q.y, n2, acc.w);
        p = __half22float2(*(const __half2*)&v3.x); q = __half22float2(*(const __half2*)&v3.y);
        acc.x = fmaf(p.x, n3, acc.x); acc.y = fmaf(p.y, n3, acc.y);
        acc.z = fmaf(q.x, n3, acc.z); acc.w = fmaf(q.y, n3, acc.w);
    }
    for (; j < cnt; j++) {
        int2 e0 = __ldg(&g_csr[beg + j]);
        uint2 v0 = __ldg(&A[e0.x * 16 + c]);
        float n0 = __int_as_float(e0.y);
        float2 p = __half22float2(*(const __half2*)&v0.x);
        float2 q = __half22float2(*(const __half2*)&v0.y);
        acc.x = fmaf(p.x, n0, acc.x); acc.y = fmaf(p.y, n0, acc.y);
        acc.z = fmaf(q.x, n0, acc.z); acc.w = fmaf(q.y, n0, acc.w);
    }

    __half2 h0 = __floats2half2_rn(acc.x, acc.y);
    __half2 h1 = __floats2half2_rn(acc.z, acc.w);
    uint2 outv;
    outv.x = *(const unsigned*)&h0;
    outv.y = *(const unsigned*)&h1;
    ((uint2*)g_bufB)[node * 16 + c] = outv;
}

// ---------------- 64x64 GEMM, fused input bias+ReLU: bufB(f16) -> bufA(f16)
__global__ __launch_bounds__(256) void gemm64_kernel(const float* __restrict__ bias_in,
                                                     const float* __restrict__ W, int n) {
    __shared__ __align__(16) float xs[4 * 64];
    int f = threadIdx.x & 63;
    int ty = threadIdx.x >> 6;

    float wcol[64];
#pragma unroll
    for (int k = 0; k < 64; k++) wcol[k] = W[k * 64 + f];

    for (int base = blockIdx.x * 4; base < n; base += gridDim.x * 4) {
        int node = base + ty;
        float v = 0.0f;
        if (node < n)
            v = fmaxf(__half2float(g_bufB[node * 64 + f]) + bias_in[f], 0.0f);
        xs[ty * 64 + f] = v;
        __syncthreads();

        float acc = 0.0f;
        const float4* xr = (const float4*)&xs[ty * 64];
#pragma unroll
        for (int k4 = 0; k4 < 16; k4++) {
            float4 xv = xr[k4];
            acc = fmaf(xv.x, wcol[4 * k4 + 0], acc);
            acc = fmaf(xv.y, wcol[4 * k4 + 1], acc);
            acc = fmaf(xv.z, wcol[4 * k4 + 2], acc);
            acc = fmaf(xv.w, wcol[4 * k4 + 3], acc);
        }
        if (node < n) g_bufA[node * 64 + f] = __float2half_rn(acc);
        __syncthreads();
    }
}

// ---------------- fused last GEMM + MLP head ----------------
__global__ __launch_bounds__(256) void gemm64_mlp_kernel(const float* __restrict__ b3,
                                                         const float* __restrict__ Wm1,
                                                         const float* __restrict__ bm1,
                                                         const float* __restrict__ Wm2,
                                                         const float* __restrict__ bm2,
                                                         float* __restrict__ out, int n) {
    __shared__ __align__(16) float xs[4 * 64];
    __shared__ float psum[8];
    int f = threadIdx.x & 63;
    int ty = threadIdx.x >> 6;
    int lane = threadIdx.x & 31;
    int wh = (threadIdx.x >> 5) & 1;

    float wcol[64];
#pragma unroll
    for (int k = 0; k < 64; k++) wcol[k] = Wm1[k * 64 + f];
    float bm1f = bm1[f];
    float wm2f = Wm2[f];
    float bm2v = bm2[0];

    for (int base = blockIdx.x * 4; base < n; base += gridDim.x * 4) {
        int node = base + ty;
        float v = 0.0f;
        if (node < n)
            v = fmaxf(__half2float(g_bufB[node * 64 + f]) + b3[f], 0.0f);
        xs[ty * 64 + f] = v;
        __syncthreads();

        float acc = 0.0f;
        const float4* xr = (const float4*)&xs[ty * 64];
#pragma unroll
        for (int k4 = 0; k4 < 16; k4++) {
            float4 xv = xr[k4];
            acc = fmaf(xv.x, wcol[4 * k4 + 0], acc);
            acc = fmaf(xv.y, wcol[4 * k4 + 1], acc);
            acc = fmaf(xv.z, wcol[4 * k4 + 2], acc);
            acc = fmaf(xv.w, wcol[4 * k4 + 3], acc);
        }
        float hpart = fmaxf(acc + bm1f, 0.0f) * wm2f;
#pragma unroll
        for (int o = 16; o > 0; o >>= 1)
            hpart += __shfl_xor_sync(0xffffffffu, hpart, o);
        if (lane == 0) psum[ty * 2 + wh] = hpart;
        __syncthreads();
        if (f == 0 && node < n) {
            float z = psum[ty * 2] + psum[ty * 2 + 1] + bm2v;
            out[node] = 1.0f / (1.0f + __expf(-z));
        }
        __syncthreads();
    }
}

// ---------------- launch ----------------
extern "C" void kernel_launch(void* const* d_in, const int* in_sizes, int n_in,
                              void* d_out, int out_size) {
    const float* x    = (const float*)d_in[0];
    const int*   ei32 = (const int*)d_in[1];
    const float* W1  = (const float*)d_in[2];
    const float* b1  = (const float*)d_in[3];
    const float* W2  = (const float*)d_in[4];
    const float* b2  = (const float*)d_in[5];
    const float* W3  = (const float*)d_in[6];
    const float* b3  = (const float*)d_in[7];
    const float* Wm1 = (const float*)d_in[8];
    const float* bm1 = (const float*)d_in[9];
    const float* Wm2 = (const float*)d_in[10];
    const float* bm2 = (const float*)d_in[11];
    float* out = (float*)d_out;

    int n = in_sizes[0] / 3;   // 100000
    int e = in_sizes[1] / 2;   // 1600000

    const int T = 256;
    int gN   = (n + T - 1) / T;
    int gE   = (e + T - 1) / T;
    int gNF  = (n * 64 + T - 1) / T;
    int gGA  = (n * 16 + T - 1) / T;
    int gGemm = 592;
    int nb = gN;

    // ---- CSR build ----
    detect_kernel<<<1, 32>>>(ei32);
    zero_cnt_kernel<<<gN, T>>>(n);
    count_kernel<<<gE, T>>>(ei32, e);
    scan1_kernel<<<nb, 256>>>(n);
    scan2_kernel<<<1, 512>>>(nb);
    scan3_kernel<<<nb, 256>>>(n);
    fill_kernel<<<gE, T>>>(ei32, e);

    // ---- layer 1 ----
    gemm_in3_kernel<<<gNF, T>>>(x, W1, n);
    gather_kernel<<<gGA, T>>>(n);
    // ---- layer 2 ----
    gemm64_kernel<<<gGemm, T>>>(b1, W2, n);
    gather_kernel<<<gGA, T>>>(n);
    // ---- layer 3 ----
    gemm64_kernel<<<gGemm, T>>>(b2, W3, n);
    gather_kernel<<<gGA, T>>>(n);
    // ---- fused last GEMM + MLP head ----
    gemm64_mlp_kernel<<<gGemm, T>>>(b3, Wm1, bm1, Wm2, bm2, out, n);
}

// round 15
// speedup vs baseline: 1.1782x; 1.1611x over previous
#include <cuda_runtime.h>
#include <cuda_fp16.h>

// Problem constants: N=100000 nodes, E=1600000 edges, HID=64
#define MAXN 100000
#define MAXE 1600000
#define HID 64
#define NB_SCAN ((MAXN + 255) / 256)   // 391 scan blocks

// ---------------- scratch (no allocations allowed) ----------------
__device__ int g_is64;
__device__ __align__(16) int    g_cnt[MAXN];
__device__ __align__(16) int    g_rowstart[MAXN];
__device__ __align__(16) int    g_cursor[MAXN];
__device__ __align__(16) int    g_bsum[NB_SCAN + 1];
__device__ __align__(16) int2   g_csr[MAXE];        // {src, norm bits}
__device__ __align__(16) float  g_dinv[MAXN];
__device__ __align__(16) __half g_bufA[MAXN * HID]; // features (gather source, fp16)
__device__ __align__(16) float  g_bufB[MAXN * HID]; // aggregated (GEMM input, fp32)

// ---------------- edge-index dtype detection (one warp) ----------------
// int64 values < 2^31 have all-zero odd 32-bit words (little-endian).
__global__ void detect_kernel(const int* __restrict__ ei32) {
    int lane = threadIdx.x;
    int v = ei32[2 * (lane * 2) + 1] | ei32[2 * (lane * 2 + 1) + 1];
    int allzero = __all_sync(0xffffffffu, v == 0);
    if (lane == 0) g_is64 = allzero;
}

__global__ void zero_cnt_kernel(int n) {
    int i = blockIdx.x * blockDim.x + threadIdx.x;
    if (i < n) g_cnt[i] = 0;
}

__global__ void count_kernel(const int* __restrict__ ei32, int e) {
    int i = blockIdx.x * blockDim.x + threadIdx.x;
    if (i >= e) return;
    int d;
    if (g_is64) d = (int)((const long long*)ei32)[e + i];
    else        d = ei32[e + i];
    atomicAdd(&g_cnt[d], 1);
}

// ---------------- prefix scan (dinv fused into pass 1) ----------------
__global__ void scan1_kernel(int n) {
    __shared__ int wsum[8];
    int i = blockIdx.x * 256 + threadIdx.x;
    int lane = threadIdx.x & 31, w = threadIdx.x >> 5;
    int v = (i < n) ? g_cnt[i] : 0;
    if (i < n) g_dinv[i] = rsqrtf((float)v + 1.0f);  // +1 = self loop
    int s = v;
#pragma unroll
    for (int o = 1; o < 32; o <<= 1) {
        int t = __shfl_up_sync(0xffffffffu, s, o);
        if (lane >= o) s += t;
    }
    if (lane == 31) wsum[w] = s;
    __syncthreads();
    if (w == 0) {
        int ws = (lane < 8) ? wsum[lane] : 0;
#pragma unroll
        for (int o = 1; o < 8; o <<= 1) {
            int t = __shfl_up_sync(0xffffffffu, ws, o);
            if (lane >= o) ws += t;
        }
        if (lane < 8) wsum[lane] = ws;
    }
    __syncthreads();
    int incl = s + ((w > 0) ? wsum[w - 1] : 0);
    if (i < n) g_rowstart[i] = incl - v;
    if (threadIdx.x == 255) g_bsum[blockIdx.x] = incl;
}

__global__ void scan2_kernel(int nb) {
    __shared__ int wsum[16];
    int tid = threadIdx.x;
    int lane = tid & 31, w = tid >> 5;
    int v = (tid < nb) ? g_bsum[tid] : 0;
    int s = v;
#pragma unroll
    for (int o = 1; o < 32; o <<= 1) {
        int t = __shfl_up_sync(0xffffffffu, s, o);
        if (lane >= o) s += t;
    }
    if (lane == 31) wsum[w] = s;
    __syncthreads();
    if (w == 0) {
        int ws = (lane < 16) ? wsum[lane] : 0;
#pragma unroll
        for (int o = 1; o < 16; o <<= 1) {
            int t = __shfl_up_sync(0xffffffffu, ws, o);
            if (lane >= o) ws += t;
        }
        if (lane < 16) wsum[lane] = ws;
    }
    __syncthreads();
    int incl = s + ((w > 0) ? wsum[w - 1] : 0);
    if (tid < nb) g_bsum[tid] = incl - v;
}

__global__ void scan3_kernel(int n) {
    int i = blockIdx.x * 256 + threadIdx.x;
    if (i < n) {
        int rs = g_rowstart[i] + g_bsum[blockIdx.x];
        g_rowstart[i] = rs;
        g_cursor[i] = rs;
    }
}

// ---------------- CSR fill ----------------
__global__ void fill_kernel(const int* __restrict__ ei32, int e) {
    int i = blockIdx.x * blockDim.x + threadIdx.x;
    if (i >= e) return;
    int s, d;
    if (g_is64) {
        const long long* e64 = (const long long*)ei32;
        s = (int)e64[i];
        d = (int)e64[e + i];
    } else {
        s = ei32[i];
        d = ei32[e + i];
    }
    int pos = atomicAdd(&g_cursor[d], 1);
    float nrm = g_dinv[s] * g_dinv[d];
    g_csr[pos] = make_int2(s, __float_as_int(nrm));
}

// ---------------- layer 1 GEMM: x(N,3) @ W1(3,64) -> bufA (fp16) ----------
__global__ void gemm_in3_kernel(const float* __restrict__ x,
                                const float* __restrict__ W1, int n) {
    int idx = blockIdx.x * blockDim.x + threadIdx.x;
    int node = idx >> 6;
    int f = idx & 63;
    if (node >= n) return;
    float x0 = x[node * 3 + 0];
    float x1 = x[node * 3 + 1];
    float x2 = x[node * 3 + 2];
    float acc = fmaf(x0, W1[f], fmaf(x1, W1[64 + f], x2 * W1[128 + f]));
    g_bufA[node * 64 + f] = __float2half_rn(acc);
}

// ---------------- CSR gather: 16 lanes/node, unroll x4, fp32 store --------
// lane c owns features [4c,4c+4). bufB[d] = sum bufA[s]*norm + self (no bias).
__global__ __launch_bounds__(256) void gather_kernel(int n) {
    int idx = blockIdx.x * blockDim.x + threadIdx.x;
    int node = idx >> 4;
    int c = idx & 15;
    if (node >= n) return;
    int beg = g_rowstart[node];
    int cnt = g_cnt[node];
    const uint2* __restrict__ A = (const uint2*)g_bufA;  // row = 16 uint2

    float di = g_dinv[node];
    float s2 = di * di;
    uint2 sv = __ldg(&A[node * 16 + c]);
    float2 a0 = __half22float2(*(const __half2*)&sv.x);
    float2 a1 = __half22float2(*(const __half2*)&sv.y);
    float4 acc = make_float4(a0.x * s2, a0.y * s2, a1.x * s2, a1.y * s2);

    int j = 0;
    for (; j + 3 < cnt; j += 4) {
        int2 e0 = __ldg(&g_csr[beg + j]);
        int2 e1 = __ldg(&g_csr[beg + j + 1]);
        int2 e2 = __ldg(&g_csr[beg + j + 2]);
        int2 e3 = __ldg(&g_csr[beg + j + 3]);
        uint2 v0 = __ldg(&A[e0.x * 16 + c]);
        uint2 v1 = __ldg(&A[e1.x * 16 + c]);
        uint2 v2 = __ldg(&A[e2.x * 16 + c]);
        uint2 v3 = __ldg(&A[e3.x * 16 + c]);
        float n0 = __int_as_float(e0.y), n1 = __int_as_float(e1.y);
        float n2 = __int_as_float(e2.y), n3 = __int_as_float(e3.y);
        float2 p, q;
        p = __half22float2(*(const __half2*)&v0.x); q = __half22float2(*(const __half2*)&v0.y);
        acc.x = fmaf(p.x, n0, acc.x); acc.y = fmaf(p.y, n0, acc.y);
        acc.z = fmaf(q.x, n0, acc.z); acc.w = fmaf(q.y, n0, acc.w);
        p = __half22float2(*(const __half2*)&v1.x); q = __half22float2(*(const __half2*)&v1.y);
        acc.x = fmaf(p.x, n1, acc.x); acc.y = fmaf(p.y, n1, acc.y);
        acc.z = fmaf(q.x, n1, acc.z); acc.w = fmaf(q.y, n1, acc.w);
        p = __half22float2(*(const __half2*)&v2.x); q = __half22float2(*(const __half2*)&v2.y);
        acc.x = fmaf(p.x, n2, acc.x); acc.y = fmaf(p.y, n2, acc.y);
        acc.z = fmaf(q.x, n2, acc.z); acc.w = fmaf(q.y, n2, acc.w);
        p = __half22float2(*(const __half2*)&v3.x); q = __half22float2(*(const __half2*)&v3.y);
        acc.x = fmaf(p.x, n3, acc.x); acc.y = fmaf(p.y, n3, acc.y);
        acc.z = fmaf(q.x, n3, acc.z); acc.w = fmaf(q.y, n3, acc.w);
    }
    for (; j < cnt; j++) {
        int2 e0 = __ldg(&g_csr[beg + j]);
        uint2 v0 = __ldg(&A[e0.x * 16 + c]);
        float n0 = __int_as_float(e0.y);
        float2 p = __half22float2(*(const __half2*)&v0.x);
        float2 q = __half22float2(*(const __half2*)&v0.y);
        acc.x = fmaf(p.x, n0, acc.x); acc.y = fmaf(p.y, n0, acc.y);
        acc.z = fmaf(q.x, n0, acc.z); acc.w = fmaf(q.y, n0, acc.w);
    }
    ((float4*)g_bufB)[node * 16 + c] = acc;
}

// ---------------- 64x64 GEMM, fused input bias+ReLU: bufB(f32) -> bufA(f16)
// 8 nodes per block-iteration: each thread computes 2 outputs, reusing wcol.
__global__ __launch_bounds__(256) void gemm64_kernel(const float* __restrict__ bias_in,
                                                     const float* __restrict__ W, int n) {
    __shared__ __align__(16) float xs[8 * 64];
    int f = threadIdx.x & 63;
    int ty = threadIdx.x >> 6;  // 0..3

    float wcol[64];
#pragma unroll
    for (int k = 0; k < 64; k++) wcol[k] = W[k * 64 + f];
    float bf = bias_in[f];

    for (int base = blockIdx.x * 8; base < n; base += gridDim.x * 8) {
        int n0 = base + ty;
        int n1 = base + 4 + ty;
        float v0 = 0.0f, v1 = 0.0f;
        if (n0 < n) v0 = fmaxf(g_bufB[n0 * 64 + f] + bf, 0.0f);
        if (n1 < n) v1 = fmaxf(g_bufB[n1 * 64 + f] + bf, 0.0f);
        xs[ty * 64 + f] = v0;
        xs[(ty + 4) * 64 + f] = v1;
        __syncthreads();

        float acc0 = 0.0f, acc1 = 0.0f;
        const float4* x0 = (const float4*)&xs[ty * 64];
        const float4* x1 = (const float4*)&xs[(ty + 4) * 64];
#pragma unroll
        for (int k4 = 0; k4 < 16; k4++) {
            float4 a = x0[k4];
            float4 b = x1[k4];
            float w0 = wcol[4 * k4 + 0], w1 = wcol[4 * k4 + 1];
            float w2 = wcol[4 * k4 + 2], w3 = wcol[4 * k4 + 3];
            acc0 = fmaf(a.x, w0, acc0); acc1 = fmaf(b.x, w0, acc1);
            acc0 = fmaf(a.y, w1, acc0); acc1 = fmaf(b.y, w1, acc1);
            acc0 = fmaf(a.z, w2, acc0); acc1 = fmaf(b.z, w2, acc1);
            acc0 = fmaf(a.w, w3, acc0); acc1 = fmaf(b.w, w3, acc1);
        }
        if (n0 < n) g_bufA[n0 * 64 + f] = __float2half_rn(acc0);
        if (n1 < n) g_bufA[n1 * 64 + f] = __float2half_rn(acc1);
        __syncthreads();
    }
}

// ---------------- MLP head: relu(bufA + bm1) @ Wm2 + bm2 -> sigmoid --------
__global__ void mlp_out_kernel(const float* __restrict__ bm1,
                               const float* __restrict__ Wm2,
                               const float* __restrict__ bm2,
                               float* __restrict__ out, int n) {
    int gtid = blockIdx.x * blockDim.x + threadIdx.x;
    int node = gtid >> 5;
    int lane = gtid & 31;
    if (node >= n) return;
    float h0 = fmaxf(__half2float(g_bufA[node * 64 + lane]) + bm1[lane], 0.0f);
    float h1 = fmaxf(__half2float(g_bufA[node * 64 + 32 + lane]) + bm1[32 + lane], 0.0f);
    float acc = fmaf(h0, Wm2[lane], h1 * Wm2[32 + lane]);
#pragma unroll
    for (int o = 16; o > 0; o >>= 1) acc += __shfl_xor_sync(0xffffffffu, acc, o);
    if (lane == 0) {
        float z = acc + bm2[0];
        out[node] = 1.0f / (1.0f + __expf(-z));
    }
}

// ---------------- launch ----------------
extern "C" void kernel_launch(void* const* d_in, const int* in_sizes, int n_in,
                              void* d_out, int out_size) {
    const float* x    = (const float*)d_in[0];
    const int*   ei32 = (const int*)d_in[1];
    const float* W1  = (const float*)d_in[2];
    const float* b1  = (const float*)d_in[3];
    const float* W2  = (const float*)d_in[4];
    const float* b2  = (const float*)d_in[5];
    const float* W3  = (const float*)d_in[6];
    const float* b3  = (const float*)d_in[7];
    const float* Wm1 = (const float*)d_in[8];
    const float* bm1 = (const float*)d_in[9];
    const float* Wm2 = (const float*)d_in[10];
    const float* bm2 = (const float*)d_in[11];
    float* out = (float*)d_out;

    int n = in_sizes[0] / 3;   // 100000
    int e = in_sizes[1] / 2;   // 1600000

    const int T = 256;
    int gN   = (n + T - 1) / T;
    int gE   = (e + T - 1) / T;
    int gNF  = (n * 64 + T - 1) / T;
    int gGA  = (n * 16 + T - 1) / T;
    int gMLP = (n * 32 + T - 1) / T;
    int gGemm = 592;
    int nb = gN;  // scan blocks

    // ---- CSR build ----
    detect_kernel<<<1, 32>>>(ei32);
    zero_cnt_kernel<<<gN, T>>>(n);
    count_kernel<<<gE, T>>>(ei32, e);
    scan1_kernel<<<nb, 256>>>(n);      // also writes dinv
    scan2_kernel<<<1, 512>>>(nb);
    scan3_kernel<<<nb, 256>>>(n);
    fill_kernel<<<gE, T>>>(ei32, e);

    // ---- layer 1 ----
    gemm_in3_kernel<<<gNF, T>>>(x, W1, n);
    gather_kernel<<<gGA, T>>>(n);
    // ---- layer 2 ----
    gemm64_kernel<<<gGemm, T>>>(b1, W2, n);
    gather_kernel<<<gGA, T>>>(n);
    // ---- layer 3 ----
    gemm64_kernel<<<gGemm, T>>>(b2, W3, n);
    gather_kernel<<<gGA, T>>>(n);
    // ---- MLP head ----
    gemm64_kernel<<<gGemm, T>>>(b3, Wm1, n);
    mlp_out_kernel<<<gMLP, T>>>(bm1, Wm2, bm2, out, n);
}

// round 17
// speedup vs baseline: 1.2637x; 1.0726x over previous
#include <cuda_runtime.h>
#include <cuda_fp16.h>

// Problem constants: N=100000 nodes, E=1600000 edges, HID=64
#define MAXN 100000
#define MAXE 1600000
#define HID 64
#define NB_SCAN ((MAXN + 255) / 256)   // 391 scan blocks

// ---------------- scratch (no allocations allowed) ----------------
__device__ int g_is64;
__device__ __align__(16) int    g_cnt[MAXN];
__device__ __align__(16) int    g_rowstart[MAXN];
__device__ __align__(16) int    g_cursor[MAXN];
__device__ __align__(16) int    g_bsum[NB_SCAN + 1];
__device__ __align__(16) int2   g_csr[MAXE];        // {src, norm bits}
__device__ __align__(16) float  g_dinv[MAXN];
__device__ __align__(16) __half g_bufA[MAXN * HID]; // features (gather source, fp16)
__device__ __align__(16) float  g_bufB[MAXN * HID]; // aggregated (GEMM input, fp32)

// ---------------- init: zero counts + edge-dtype detect (merged) ----------
// int64 values < 2^31 have all-zero odd 32-bit words (little-endian).
__global__ void init_kernel(const int* __restrict__ ei32, int n) {
    int i = blockIdx.x * blockDim.x + threadIdx.x;
    if (i < n) g_cnt[i] = 0;
    if (blockIdx.x == 0 && threadIdx.x < 32) {
        int lane = threadIdx.x;
        int v = ei32[2 * (lane * 2) + 1] | ei32[2 * (lane * 2 + 1) + 1];
        int allzero = __all_sync(0xffffffffu, v == 0);
        if (lane == 0) g_is64 = allzero;
    }
}

__global__ void count_kernel(const int* __restrict__ ei32, int e) {
    int i = blockIdx.x * blockDim.x + threadIdx.x;
    if (i >= e) return;
    int d;
    if (g_is64) d = (int)((const long long*)ei32)[e + i];
    else        d = ei32[e + i];
    atomicAdd(&g_cnt[d], 1);
}

// ---------------- prefix scan (dinv fused into pass 1) ----------------
__global__ void scan1_kernel(int n) {
    __shared__ int wsum[8];
    int i = blockIdx.x * 256 + threadIdx.x;
    int lane = threadIdx.x & 31, w = threadIdx.x >> 5;
    int v = (i < n) ? g_cnt[i] : 0;
    if (i < n) g_dinv[i] = rsqrtf((float)v + 1.0f);  // +1 = self loop
    int s = v;
#pragma unroll
    for (int o = 1; o < 32; o <<= 1) {
        int t = __shfl_up_sync(0xffffffffu, s, o);
        if (lane >= o) s += t;
    }
    if (lane == 31) wsum[w] = s;
    __syncthreads();
    if (w == 0) {
        int ws = (lane < 8) ? wsum[lane] : 0;
#pragma unroll
        for (int o = 1; o < 8; o <<= 1) {
            int t = __shfl_up_sync(0xffffffffu, ws, o);
            if (lane >= o) ws += t;
        }
        if (lane < 8) wsum[lane] = ws;
    }
    __syncthreads();
    int incl = s + ((w > 0) ? wsum[w - 1] : 0);
    if (i < n) g_rowstart[i] = incl - v;
    if (threadIdx.x == 255) g_bsum[blockIdx.x] = incl;
}

__global__ void scan2_kernel(int nb) {
    __shared__ int wsum[16];
    int tid = threadIdx.x;
    int lane = tid & 31, w = tid >> 5;
    int v = (tid < nb) ? g_bsum[tid] : 0;
    int s = v;
#pragma unroll
    for (int o = 1; o < 32; o <<= 1) {
        int t = __shfl_up_sync(0xffffffffu, s, o);
        if (lane >= o) s += t;
    }
    if (lane == 31) wsum[w] = s;
    __syncthreads();
    if (w == 0) {
        int ws = (lane < 16) ? wsum[lane] : 0;
#pragma unroll
        for (int o = 1; o < 16; o <<= 1) {
            int t = __shfl_up_sync(0xffffffffu, ws, o);
            if (lane >= o) ws += t;
        }
        if (lane < 16) wsum[lane] = ws;
    }
    __syncthreads();
    int incl = s + ((w > 0) ? wsum[w - 1] : 0);
    if (tid < nb) g_bsum[tid] = incl - v;
}

__global__ void scan3_kernel(int n) {
    int i = blockIdx.x * 256 + threadIdx.x;
    if (i < n) {
        int rs = g_rowstart[i] + g_bsum[blockIdx.x];
        g_rowstart[i] = rs;
        g_cursor[i] = rs;
    }
}

// ---------------- CSR fill ----------------
__global__ void fill_kernel(const int* __restrict__ ei32, int e) {
    int i = blockIdx.x * blockDim.x + threadIdx.x;
    if (i >= e) return;
    int s, d;
    if (g_is64) {
        const long long* e64 = (const long long*)ei32;
        s = (int)e64[i];
        d = (int)e64[e + i];
    } else {
        s = ei32[i];
        d = ei32[e + i];
    }
    int pos = atomicAdd(&g_cursor[d], 1);
    float nrm = g_dinv[s] * g_dinv[d];
    g_csr[pos] = make_int2(s, __float_as_int(nrm));
}

// ---------------- layer 1 GEMM: x(N,3) @ W1(3,64) -> bufA (fp16) ----------
__global__ void gemm_in3_kernel(const float* __restrict__ x,
                                const float* __restrict__ W1, int n) {
    int idx = blockIdx.x * blockDim.x + threadIdx.x;
    int node = idx >> 6;
    int f = idx & 63;
    if (node >= n) return;
    float x0 = x[node * 3 + 0];
    float x1 = x[node * 3 + 1];
    float x2 = x[node * 3 + 2];
    float acc = fmaf(x0, W1[f], fmaf(x1, W1[64 + f], x2 * W1[128 + f]));
    g_bufA[node * 64 + f] = __float2half_rn(acc);
}

// ---------------- CSR gather: 8 lanes/node, 16B loads, unroll x4 ----------
// lane c owns features [8c,8c+8) (8 halves = 16 B). fp32 acc, fp32 store.
__device__ __forceinline__ void fma8(float* acc, uint4 v, float nm) {
    float2 p;
    p = __half22float2(*(const __half2*)&v.x);
    acc[0] = fmaf(p.x, nm, acc[0]); acc[1] = fmaf(p.y, nm, acc[1]);
    p = __half22float2(*(const __half2*)&v.y);
    acc[2] = fmaf(p.x, nm, acc[2]); acc[3] = fmaf(p.y, nm, acc[3]);
    p = __half22float2(*(const __half2*)&v.z);
    acc[4] = fmaf(p.x, nm, acc[4]); acc[5] = fmaf(p.y, nm, acc[5]);
    p = __half22float2(*(const __half2*)&v.w);
    acc[6] = fmaf(p.x, nm, acc[6]); acc[7] = fmaf(p.y, nm, acc[7]);
}

__global__ __launch_bounds__(256) void gather_kernel(int n) {
    int idx = blockIdx.x * blockDim.x + threadIdx.x;
    int node = idx >> 3;
    int c = idx & 7;
    if (node >= n) return;
    int beg = g_rowstart[node];
    int cnt = g_cnt[node];
    const uint4* __restrict__ A = (const uint4*)g_bufA;  // row = 8 uint4

    float di = g_dinv[node];
    float s2 = di * di;
    float acc[8];
    {
        uint4 sv = __ldg(&A[node * 8 + c]);
        float2 p;
        p = __half22float2(*(const __half2*)&sv.x); acc[0] = p.x * s2; acc[1] = p.y * s2;
        p = __half22float2(*(const __half2*)&sv.y); acc[2] = p.x * s2; acc[3] = p.y * s2;
        p = __half22float2(*(const __half2*)&sv.z); acc[4] = p.x * s2; acc[5] = p.y * s2;
        p = __half22float2(*(const __half2*)&sv.w); acc[6] = p.x * s2; acc[7] = p.y * s2;
    }

    int j = 0;
    for (; j + 3 < cnt; j += 4) {
        int2 e0 = __ldg(&g_csr[beg + j]);
        int2 e1 = __ldg(&g_csr[beg + j + 1]);
        int2 e2 = __ldg(&g_csr[beg + j + 2]);
        int2 e3 = __ldg(&g_csr[beg + j + 3]);
        uint4 v0 = __ldg(&A[e0.x * 8 + c]);
        uint4 v1 = __ldg(&A[e1.x * 8 + c]);
        uint4 v2 = __ldg(&A[e2.x * 8 + c]);
        uint4 v3 = __ldg(&A[e3.x * 8 + c]);
        fma8(acc, v0, __int_as_float(e0.y));
        fma8(acc, v1, __int_as_float(e1.y));
        fma8(acc, v2, __int_as_float(e2.y));
        fma8(acc, v3, __int_as_float(e3.y));
    }
    for (; j < cnt; j++) {
        int2 e0 = __ldg(&g_csr[beg + j]);
        uint4 v0 = __ldg(&A[e0.x * 8 + c]);
        fma8(acc, v0, __int_as_float(e0.y));
    }

    float4* outp = (float4*)&g_bufB[node * 64 + c * 8];
    outp[0] = make_float4(acc[0], acc[1], acc[2], acc[3]);
    outp[1] = make_float4(acc[4], acc[5], acc[6], acc[7]);
}

// ---------------- 64x64 GEMM, fused input bias+ReLU: bufB(f32) -> bufA(f16)
// 8 nodes per block-iteration: each thread computes 2 outputs, reusing wcol.
__global__ __launch_bounds__(256) void gemm64_kernel(const float* __restrict__ bias_in,
                                                     const float* __restrict__ W, int n) {
    __shared__ __align__(16) float xs[8 * 64];
    int f = threadIdx.x & 63;
    int ty = threadIdx.x >> 6;  // 0..3

    float wcol[64];
#pragma unroll
    for (int k = 0; k < 64; k++) wcol[k] = W[k * 64 + f];
    float bf = bias_in[f];

    for (int base = blockIdx.x * 8; base < n; base += gridDim.x * 8) {
        int n0 = base + ty;
        int n1 = base + 4 + ty;
        float v0 = 0.0f, v1 = 0.0f;
        if (n0 < n) v0 = fmaxf(g_bufB[n0 * 64 + f] + bf, 0.0f);
        if (n1 < n) v1 = fmaxf(g_bufB[n1 * 64 + f] + bf, 0.0f);
        xs[ty * 64 + f] = v0;
        xs[(ty + 4) * 64 + f] = v1;
        __syncthreads();

        float acc0 = 0.0f, acc1 = 0.0f;
        const float4* x0 = (const float4*)&xs[ty * 64];
        const float4* x1 = (const float4*)&xs[(ty + 4) * 64];
#pragma unroll
        for (int k4 = 0; k4 < 16; k4++) {
            float4 a = x0[k4];
            float4 b = x1[k4];
            float w0 = wcol[4 * k4 + 0], w1 = wcol[4 * k4 + 1];
            float w2 = wcol[4 * k4 + 2], w3 = wcol[4 * k4 + 3];
            acc0 = fmaf(a.x, w0, acc0); acc1 = fmaf(b.x, w0, acc1);
            acc0 = fmaf(a.y, w1, acc0); acc1 = fmaf(b.y, w1, acc1);
            acc0 = fmaf(a.z, w2, acc0); acc1 = fmaf(b.z, w2, acc1);
            acc0 = fmaf(a.w, w3, acc0); acc1 = fmaf(b.w, w3, acc1);
        }
        if (n0 < n) g_bufA[n0 * 64 + f] = __float2half_rn(acc0);
        if (n1 < n) g_bufA[n1 * 64 + f] = __float2half_rn(acc1);
        __syncthreads();
    }
}

// ---------------- MLP head: relu(bufA + bm1) @ Wm2 + bm2 -> sigmoid --------
__global__ void mlp_out_kernel(const float* __restrict__ bm1,
                               const float* __restrict__ Wm2,
                               const float* __restrict__ bm2,
                               float* __restrict__ out, int n) {
    int gtid = blockIdx.x * blockDim.x + threadIdx.x;
    int node = gtid >> 5;
    int lane = gtid & 31;
    if (node >= n) return;
    float h0 = fmaxf(__half2float(g_bufA[node * 64 + lane]) + bm1[lane], 0.0f);
    float h1 = fmaxf(__half2float(g_bufA[node * 64 + 32 + lane]) + bm1[32 + lane], 0.0f);
    float acc = fmaf(h0, Wm2[lane], h1 * Wm2[32 + lane]);
#pragma unroll
    for (int o = 16; o > 0; o >>= 1) acc += __shfl_xor_sync(0xffffffffu, acc, o);
    if (lane == 0) {
        float z = acc + bm2[0];
        out[node] = 1.0f / (1.0f + __expf(-z));
    }
}

// ---------------- launch ----------------
extern "C" void kernel_launch(void* const* d_in, const int* in_sizes, int n_in,
                              void* d_out, int out_size) {
    const float* x    = (const float*)d_in[0];
    const int*   ei32 = (const int*)d_in[1];
    const float* W1  = (const float*)d_in[2];
    const float* b1  = (const float*)d_in[3];
    const float* W2  = (const float*)d_in[4];
    const float* b2  = (const float*)d_in[5];
    const float* W3  = (const float*)d_in[6];
    const float* b3  = (const float*)d_in[7];
    const float* Wm1 = (const float*)d_in[8];
    const float* bm1 = (const float*)d_in[9];
    const float* Wm2 = (const float*)d_in[10];
    const float* bm2 = (const float*)d_in[11];
    float* out = (float*)d_out;

    int n = in_sizes[0] / 3;   // 100000
    int e = in_sizes[1] / 2;   // 1600000

    const int T = 256;
    int gN   = (n + T - 1) / T;
    int gE   = (e + T - 1) / T;
    int gNF  = (n * 64 + T - 1) / T;
    int gGA  = (n * 8 + T - 1) / T;
    int gMLP = (n * 32 + T - 1) / T;
    int gGemm = 592;
    int nb = gN;  // scan blocks

    // ---- CSR build ----
    init_kernel<<<gN, T>>>(ei32, n);   // zero counts + dtype detect
    count_kernel<<<gE, T>>>(ei32, e);
    scan1_kernel<<<nb, 256>>>(n);      // also writes dinv
    scan2_kernel<<<1, 512>>>(nb);
    scan3_kernel<<<nb, 256>>>(n);
    fill_kernel<<<gE, T>>>(ei32, e);

    // ---- layer 1 ----
    gemm_in3_kernel<<<gNF, T>>>(x, W1, n);
    gather_kernel<<<gGA, T>>>(n);
    // ---- layer 2 ----
    gemm64_kernel<<<gGemm, T>>>(b1, W2, n);
    gather_kernel<<<gGA, T>>>(n);
    // ---- layer 3 ----
    gemm64_kernel<<<gGemm, T>>>(b2, W3, n);
    gather_kernel<<<gGA, T>>>(n);
    // ---- MLP head ----
    gemm64_kernel<<<gGemm, T>>>(b3, Wm1, n);
    mlp_out_kernel<<<gMLP, T>>>(bm1, Wm2, bm2, out, n);
}